// round 5
// baseline (speedup 1.0000x reference)
#include <cuda_runtime.h>

// -------------------------------------------------------------------------
// MaskedBilinearFullSymLoss — B=16, C=2, H=W=512, scalar f32 output.
// One thread = one column j, two adjacent rows (shares the middle bilinear
// row: loads 3 shifted rows, not 4). Straight-line branchless body so all
// loads front-batch. High occupancy via __launch_bounds__(512, 3).
// -------------------------------------------------------------------------

#define HH 512
#define WW 512

__device__ double g_acc;            // zero-initialized
__device__ unsigned int g_ticket;   // zero-initialized

__global__ __launch_bounds__(512, 3)
void loss_kernel(const float* __restrict__ grid,
                 const float* __restrict__ gt,
                 const float* __restrict__ gd,
                 const float* __restrict__ mask,
                 int B, unsigned int nblocks, float* __restrict__ out)
{
    const int H = HH, W = WW;
    const int b  = blockIdx.y;
    const int i0 = blockIdx.x * 2;          // two rows per block
    const int j  = threadIdx.x;             // one column per thread

    const float dx = -8.0f * gt[2 * b + 0];
    const float dy =  8.0f * gt[2 * b + 1];
    const float sym_x = gd[2 * b + 0];
    const float sym_y = gd[2 * b + 1];

    const float dx1f = floorf(dx), dy1f = floorf(dy);
    const int dx1 = (int)dx1f, dy1 = (int)dy1f;
    const int dx2 = dx1 + 1,  dy2 = dy1 + 1;
    const float wx1 = (dx1f + 1.0f) - dx, wx2 = dx - dx1f;
    const float wy1 = (dy1f + 1.0f) - dy, wy2 = dy - dy1f;
    const float w11 = wy1 * wx1, w12 = wy1 * wx2;
    const float w21 = wy2 * wx1, w22 = wy2 * wx2;

    const float* __restrict__ g0 = grid + (size_t)(2 * b + 0) * H * W;
    const float* __restrict__ g1 = grid + (size_t)(2 * b + 1) * H * W;
    const float* __restrict__ mk = mask + (size_t)b * H * W;

    const int imax = H - dy2;
    float acc = 0.0f;
    float cnt;

    if (dx > 0.0f) {
        const int jmax = W - dx2;
        cnt = (float)imax * (float)jmax;
        const float jv = (j < jmax) ? 1.0f : 0.0f;
        const float v0 = (i0     < imax) ? jv : 0.0f;
        const float v1 = (i0 + 1 < imax) ? jv : 0.0f;

        // clamped indices (exact when valid; harmless garbage * 0 otherwise)
        const int ja = min(j + dx1, W - 1);
        const int jb = min(j + dx2, W - 1);
        const int sa = min(i0 + dy1,     H - 1);
        const int sb = min(i0 + dy1 + 1, H - 1);
        const int sc = min(i0 + dy1 + 2, H - 1);

        const float* g0sa = g0 + (size_t)sa * W;
        const float* g0sb = g0 + (size_t)sb * W;
        const float* g0sc = g0 + (size_t)sc * W;
        const float* g1sa = g1 + (size_t)sa * W;
        const float* g1sb = g1 + (size_t)sb * W;
        const float* g1sc = g1 + (size_t)sc * W;

        // ---- batch all 18 loads
        float A0a = g0sa[ja], A0b = g0sa[jb];
        float B0a = g0sb[ja], B0b = g0sb[jb];
        float C0a = g0sc[ja], C0b = g0sc[jb];
        float A1a = g1sa[ja], A1b = g1sa[jb];
        float B1a = g1sb[ja], B1b = g1sb[jb];
        float C1a = g1sc[ja], C1b = g1sc[jb];
        float r00 = g0[(size_t)i0 * W + j],       r01 = g0[(size_t)(i0 + 1) * W + j];
        float r10 = g1[(size_t)i0 * W + j],       r11 = g1[(size_t)(i0 + 1) * W + j];
        float m0  = mk[(size_t)i0 * W + j],       m1  = mk[(size_t)(i0 + 1) * W + j];

        // row r = 0 uses (A, B); row r = 1 uses (B, C) — shared middle row
        float s00 = w11 * A0a + w12 * A0b + w21 * B0a + w22 * B0b;
        float s10 = w11 * A1a + w12 * A1b + w21 * B1a + w22 * B1b;
        float e0  = (r00 - s00) * sym_y + (r10 - s10) * sym_x;
        acc += v0 * m0 * e0 * e0;

        float s01 = w11 * B0a + w12 * B0b + w21 * C0a + w22 * C0b;
        float s11 = w11 * B1a + w12 * B1b + w21 * C1a + w22 * C1b;
        float e1  = (r01 - s01) * sym_y + (r11 - s11) * sym_x;
        acc += v1 * m1 * e1 * e1;
    } else {
        const int jmax = W + dx1;       // dx1 <= 0
        cnt = (float)imax * (float)jmax;
        const float jv = (j < jmax) ? 1.0f : 0.0f;
        const float v0 = (i0     < imax) ? jv : 0.0f;
        const float v1 = (i0 + 1 < imax) ? jv : 0.0f;

        const int cB  = min(j - dx1, W - 1);
        const int c1  = min(j + 1,  W - 1);
        const int rA0 = min(i0 + dy2,     H - 1);
        const int rA1 = min(i0 + dy2 + 1, H - 1);
        const int r2  = min(i0 + 2, H - 1);

        const float* g0A0 = g0 + (size_t)rA0 * W;
        const float* g0A1 = g0 + (size_t)rA1 * W;
        const float* g1A0 = g1 + (size_t)rA0 * W;
        const float* g1A1 = g1 + (size_t)rA1 * W;

        // ---- batch all 16 loads
        float F00a = g0A0[j], F00b = g0A0[c1];
        float F01a = g0A1[j], F01b = g0A1[c1];
        float F10a = g1A0[j], F10b = g1A0[c1];
        float F11a = g1A1[j], F11b = g1A1[c1];
        float S0_0 = g0[(size_t)i0 * W + cB];
        float S0_1 = g0[(size_t)(i0 + 1) * W + cB];
        float S0_2 = g0[(size_t)r2 * W + cB];
        float S1_0 = g1[(size_t)i0 * W + cB];
        float S1_1 = g1[(size_t)(i0 + 1) * W + cB];
        float S1_2 = g1[(size_t)r2 * W + cB];
        float M0   = mk[(size_t)rA0 * W + cB];
        float M1   = mk[(size_t)rA1 * W + cB];

        // row r = 0: second term rows (i0+1, i0); row r = 1: (i0+2, i0+1)
        float f00 = wx1 * F00a + wx2 * F00b;
        float f10 = wx1 * F10a + wx2 * F10b;
        float s00 = wy1 * S0_1 + wy2 * S0_0;
        float s10 = wy1 * S1_1 + wy2 * S1_0;
        float e0  = (f00 - s00) * sym_y + (f10 - s10) * sym_x;
        acc += v0 * M0 * e0 * e0;

        float f01 = wx1 * F01a + wx2 * F01b;
        float f11 = wx1 * F11a + wx2 * F11b;
        float s01 = wy1 * S0_2 + wy2 * S0_1;
        float s11 = wy1 * S1_2 + wy2 * S1_1;
        float e1  = (f01 - s01) * sym_y + (f11 - s11) * sym_x;
        acc += v1 * M1 * e1 * e1;
    }

    // ---- block reduction (512 threads = 16 warps)
    #pragma unroll
    for (int o = 16; o > 0; o >>= 1)
        acc += __shfl_down_sync(0xFFFFFFFFu, acc, o);

    __shared__ float wsum[16];
    const int lane = threadIdx.x & 31;
    const int warp = threadIdx.x >> 5;
    if (lane == 0) wsum[warp] = acc;
    __syncthreads();

    if (threadIdx.x == 0) {
        float s = 0.0f;
        #pragma unroll
        for (int k = 0; k < 16; k++) s += wsum[k];
        double scaled = (double)s / ((double)cnt * (double)B);
        atomicAdd(&g_acc, scaled);

        __threadfence();
        unsigned int prev = atomicInc(&g_ticket, nblocks - 1u);
        if (prev == nblocks - 1u) {
            double total = atomicAdd(&g_acc, 0.0);   // atomic read
            out[0] = (float)total;
            g_acc = 0.0;                              // reset for next replay
            __threadfence();
        }
    }
}

extern "C" void kernel_launch(void* const* d_in, const int* in_sizes, int n_in,
                              void* d_out, int out_size)
{
    const float* grid = (const float*)d_in[0];
    const float* gt   = (const float*)d_in[1];
    const float* gd   = (const float*)d_in[2];
    const float* mask = (const float*)d_in[3];
    float* out = (float*)d_out;

    const int B = in_sizes[1] / 2;   // gt_sym_axis is (B, 2)

    dim3 g(HH / 2, B);
    unsigned int nblocks = (HH / 2) * B;
    loss_kernel<<<g, 512>>>(grid, gt, gd, mask, B, nblocks, out);
}

// round 6
// speedup vs baseline: 1.6038x; 1.6038x over previous
#include <cuda_runtime.h>

// -------------------------------------------------------------------------
// MaskedBilinearFullSymLoss — B=16, C=2, H=W=512, scalar f32 output.
// 256 thr/block, 4 rows/block with ROW SHARING (5 shifted rows serve 4
// output rows), 2 sequential column iterations => 8 px/thread.
// All loads per column-iteration front-batched (30-32 LDG) for high MLP.
// -------------------------------------------------------------------------

#define HH 512
#define WW 512

__device__ double g_acc;            // zero-initialized
__device__ unsigned int g_ticket;   // zero-initialized

__global__ __launch_bounds__(256, 4)
void loss_kernel(const float* __restrict__ grid,
                 const float* __restrict__ gt,
                 const float* __restrict__ gd,
                 const float* __restrict__ mask,
                 int B, unsigned int nblocks, float* __restrict__ out)
{
    const int H = HH, W = WW;
    const int b   = blockIdx.y;
    const int i0  = blockIdx.x * 4;          // 4 output rows per block
    const int tid = threadIdx.x;

    const float dx = -8.0f * gt[2 * b + 0];
    const float dy =  8.0f * gt[2 * b + 1];
    const float sym_x = gd[2 * b + 0];
    const float sym_y = gd[2 * b + 1];

    const float dx1f = floorf(dx), dy1f = floorf(dy);
    const int dx1 = (int)dx1f, dy1 = (int)dy1f;
    const int dx2 = dx1 + 1,  dy2 = dy1 + 1;
    const float wx1 = (dx1f + 1.0f) - dx, wx2 = dx - dx1f;
    const float wy1 = (dy1f + 1.0f) - dy, wy2 = dy - dy1f;
    const float w11 = wy1 * wx1, w12 = wy1 * wx2;
    const float w21 = wy2 * wx1, w22 = wy2 * wx2;

    const float* __restrict__ g0 = grid + (size_t)(2 * b + 0) * H * W;
    const float* __restrict__ g1 = grid + (size_t)(2 * b + 1) * H * W;
    const float* __restrict__ mk = mask + (size_t)b * H * W;

    const int imax = H - dy2;
    float acc = 0.0f;
    float cnt;

    // row validity multipliers (same for both branches)
    float rv[4];
    #pragma unroll
    for (int r = 0; r < 4; r++) rv[r] = (i0 + r < imax) ? 1.0f : 0.0f;

    if (dx > 0.0f) {
        const int jmax = W - dx2;
        cnt = (float)imax * (float)jmax;

        // 5 shared shifted-row offsets (dy1 >= 0 in this branch)
        int os[5];
        #pragma unroll
        for (int t = 0; t < 5; t++) os[t] = min(i0 + dy1 + t, H - 1) * W;
        // 4 center/mask row offsets (always in-bounds: i0+3 <= 511)
        int oc[4];
        #pragma unroll
        for (int r = 0; r < 4; r++) oc[r] = (i0 + r) * W;

        for (int jj = 0; jj < 2; jj++) {
            const int j = tid + jj * 256;
            const float jv = (j < jmax) ? 1.0f : 0.0f;
            const int ja = min(j + dx1, W - 1);
            const int jb = min(ja + 1,  W - 1);

            // ---- batch: 10 + 10 + 8 + 4 = 32 loads
            float s0a[5], s0b[5], s1a[5], s1b[5];
            #pragma unroll
            for (int t = 0; t < 5; t++) {
                s0a[t] = g0[os[t] + ja];  s0b[t] = g0[os[t] + jb];
                s1a[t] = g1[os[t] + ja];  s1b[t] = g1[os[t] + jb];
            }
            float c0[4], c1[4], mm[4];
            #pragma unroll
            for (int r = 0; r < 4; r++) {
                c0[r] = g0[oc[r] + j];
                c1[r] = g1[oc[r] + j];
                mm[r] = mk[oc[r] + j];
            }

            // ---- compute: row r uses shifted rows (r, r+1)
            #pragma unroll
            for (int r = 0; r < 4; r++) {
                float s0 = w11 * s0a[r] + w12 * s0b[r]
                         + w21 * s0a[r + 1] + w22 * s0b[r + 1];
                float s1 = w11 * s1a[r] + w12 * s1b[r]
                         + w21 * s1a[r + 1] + w22 * s1b[r + 1];
                float err = (c0[r] - s0) * sym_y + (c1[r] - s1) * sym_x;
                acc += (rv[r] * jv) * mm[r] * err * err;
            }
        }
    } else {
        const int jmax = W + dx1;            // dx1 <= 0
        cnt = (float)imax * (float)jmax;

        // first-term rows (i0+dy2+r) and shared second-term rows (i0+t)
        int of[4];
        #pragma unroll
        for (int r = 0; r < 4; r++) of[r] = min(i0 + dy2 + r, H - 1) * W;
        int os[5];
        #pragma unroll
        for (int t = 0; t < 5; t++) os[t] = min(i0 + t, H - 1) * W;

        for (int jj = 0; jj < 2; jj++) {
            const int j = tid + jj * 256;
            const float jv = (j < jmax) ? 1.0f : 0.0f;
            const int cB = min(j - dx1, W - 1);
            const int c1 = min(j + 1,  W - 1);

            // ---- batch: 16 + 10 + 4 = 30 loads
            float F0a[4], F0b[4], F1a[4], F1b[4], M[4];
            #pragma unroll
            for (int r = 0; r < 4; r++) {
                F0a[r] = g0[of[r] + j];  F0b[r] = g0[of[r] + c1];
                F1a[r] = g1[of[r] + j];  F1b[r] = g1[of[r] + c1];
                M[r]   = mk[of[r] + cB];
            }
            float S0[5], S1[5];
            #pragma unroll
            for (int t = 0; t < 5; t++) {
                S0[t] = g0[os[t] + cB];
                S1[t] = g1[os[t] + cB];
            }

            // ---- compute: row r second term uses shared rows (r+1, r)
            #pragma unroll
            for (int r = 0; r < 4; r++) {
                float f0 = wx1 * F0a[r] + wx2 * F0b[r];
                float f1 = wx1 * F1a[r] + wx2 * F1b[r];
                float s0 = wy1 * S0[r + 1] + wy2 * S0[r];
                float s1 = wy1 * S1[r + 1] + wy2 * S1[r];
                float err = (f0 - s0) * sym_y + (f1 - s1) * sym_x;
                acc += (rv[r] * jv) * M[r] * err * err;
            }
        }
    }

    // ---- block reduction (8 warps)
    #pragma unroll
    for (int o = 16; o > 0; o >>= 1)
        acc += __shfl_down_sync(0xFFFFFFFFu, acc, o);

    __shared__ float wsum[8];
    const int lane = tid & 31;
    const int warp = tid >> 5;
    if (lane == 0) wsum[warp] = acc;
    __syncthreads();

    if (tid == 0) {
        float s = 0.0f;
        #pragma unroll
        for (int k = 0; k < 8; k++) s += wsum[k];
        double scaled = (double)s / ((double)cnt * (double)B);
        atomicAdd(&g_acc, scaled);

        __threadfence();
        unsigned int prev = atomicInc(&g_ticket, nblocks - 1u);
        if (prev == nblocks - 1u) {
            double total = atomicAdd(&g_acc, 0.0);   // atomic read
            out[0] = (float)total;
            g_acc = 0.0;                              // reset for next replay
            __threadfence();
        }
    }
}

extern "C" void kernel_launch(void* const* d_in, const int* in_sizes, int n_in,
                              void* d_out, int out_size)
{
    const float* grid = (const float*)d_in[0];
    const float* gt   = (const float*)d_in[1];
    const float* gd   = (const float*)d_in[2];
    const float* mask = (const float*)d_in[3];
    float* out = (float*)d_out;

    const int B = in_sizes[1] / 2;   // gt_sym_axis is (B, 2)

    dim3 g(HH / 4, B);
    unsigned int nblocks = (HH / 4) * B;
    loss_kernel<<<g, 256>>>(grid, gt, gd, mask, B, nblocks, out);
}

// round 7
// speedup vs baseline: 1.7438x; 1.0873x over previous
#include <cuda_runtime.h>

// -------------------------------------------------------------------------
// MaskedBilinearFullSymLoss — B=16, C=2, H=W=512, scalar f32 output.
// 256 thr/block, 4 rows/block (row sharing), 2 consecutive cols/thread via
// float2 loads (parity-templated shifted windows) => 8 px/thread with ~36
// LDGs/thread instead of 64.
// -------------------------------------------------------------------------

#define HH 512
#define WW 512

__device__ double g_acc;            // zero-initialized
__device__ unsigned int g_ticket;   // zero-initialized

__device__ __forceinline__ float2 ld2(const float* __restrict__ p) {
    return *(const float2*)p;
}

struct Ctx {
    const float* __restrict__ g0;
    const float* __restrict__ g1;
    const float* __restrict__ mk;
    float wx1, wx2, wy1, wy2, w11, w12, w21, w22, sym_x, sym_y;
    int dx1, dy1, dy2, imax, jmax, i0, j0;
};

// 3-float shifted window [ja, ja+1, ja+2]; P = ja parity. Clamped values are
// only consumed with a zero validity factor.
template<int P>
__device__ __forceinline__ void ldwin(const float* __restrict__ row, int ja,
                                      float& x0, float& x1, float& x2) {
    if (P == 0) {
        float2 v = ld2(row + min(ja, WW - 2));
        float  s = row[min(ja + 2, WW - 1)];
        x0 = v.x; x1 = v.y; x2 = s;
    } else {
        float2 a = ld2(row + min(ja - 1, WW - 2));
        float2 b = ld2(row + min(ja + 1, WW - 2));
        x0 = a.y; x1 = b.x; x2 = b.y;
    }
}

// 2-float window [c, c+1]; Q = c parity.
template<int Q>
__device__ __forceinline__ void ldpair(const float* __restrict__ row, int c,
                                       float& y0, float& y1) {
    if (Q == 0) {
        float2 v = ld2(row + min(c, WW - 2));
        y0 = v.x; y1 = v.y;
    } else {
        y0 = row[min(c,     WW - 1)];
        y1 = row[min(c + 1, WW - 1)];
    }
}

// ---- positive branch: process output rows (ib, ib+1) for cols (j0, j0+1)
template<int P>
__device__ __forceinline__ float pos_pair(const Ctx& c, int ib) {
    const int ja = c.j0 + c.dx1;
    // 3 shifted source rows ib+dy1 .. ib+dy1+2 (row-clamped)
    int os[3];
    #pragma unroll
    for (int t = 0; t < 3; t++) os[t] = min(ib + c.dy1 + t, HH - 1) * WW;

    float X0[3], X1[3], X2[3];   // channel 0 windows
    float Y0[3], Y1[3], Y2[3];   // channel 1 windows
    #pragma unroll
    for (int t = 0; t < 3; t++) {
        ldwin<P>(c.g0 + os[t], ja, X0[t], X1[t], X2[t]);
        ldwin<P>(c.g1 + os[t], ja, Y0[t], Y1[t], Y2[t]);
    }
    float2 c0[2], c1[2], mm[2];
    #pragma unroll
    for (int r = 0; r < 2; r++) {
        const int oc = (ib + r) * WW + c.j0;     // always in-bounds
        c0[r] = ld2(c.g0 + oc);
        c1[r] = ld2(c.g1 + oc);
        mm[r] = ld2(c.mk + oc);
    }

    const float jv0 = (c.j0     < c.jmax) ? 1.0f : 0.0f;
    const float jv1 = (c.j0 + 1 < c.jmax) ? 1.0f : 0.0f;

    float acc = 0.0f;
    #pragma unroll
    for (int r = 0; r < 2; r++) {
        const float rvv = (ib + r < c.imax) ? 1.0f : 0.0f;
        // pixel j0
        float s0 = c.w11 * X0[r] + c.w12 * X1[r] + c.w21 * X0[r+1] + c.w22 * X1[r+1];
        float s1 = c.w11 * Y0[r] + c.w12 * Y1[r] + c.w21 * Y0[r+1] + c.w22 * Y1[r+1];
        float e0 = (c0[r].x - s0) * c.sym_y + (c1[r].x - s1) * c.sym_x;
        acc += (rvv * jv0) * mm[r].x * e0 * e0;
        // pixel j0+1
        float t0 = c.w11 * X1[r] + c.w12 * X2[r] + c.w21 * X1[r+1] + c.w22 * X2[r+1];
        float t1 = c.w11 * Y1[r] + c.w12 * Y2[r] + c.w21 * Y1[r+1] + c.w22 * Y2[r+1];
        float e1 = (c0[r].y - t0) * c.sym_y + (c1[r].y - t1) * c.sym_x;
        acc += (rvv * jv1) * mm[r].y * e1 * e1;
    }
    return acc;
}

// ---- negative branch: rows (ib, ib+1), cols (j0, j0+1)
template<int Q>
__device__ __forceinline__ float neg_pair(const Ctx& c, int ib) {
    const int m2  = -c.dx1;            // >= 0
    const int cB0 = c.j0 + m2;

    // first-term rows ib+dy2+r (clamped); window [j0, j0+1, min(j0+2)]
    float A0x[2], A0y[2], A0z[2], A1x[2], A1y[2], A1z[2];
    float2 M[2];
    #pragma unroll
    for (int r = 0; r < 2; r++) {
        const int of = min(ib + c.dy2 + r, HH - 1) * WW;
        float2 v0 = ld2(c.g0 + of + c.j0);
        float2 v1 = ld2(c.g1 + of + c.j0);
        A0x[r] = v0.x; A0y[r] = v0.y; A0z[r] = c.g0[of + min(c.j0 + 2, WW - 1)];
        A1x[r] = v1.x; A1y[r] = v1.y; A1z[r] = c.g1[of + min(c.j0 + 2, WW - 1)];
        ldpair<Q>(c.mk + of, cB0, M[r].x, M[r].y);
    }
    // second-term rows ib .. ib+2 (clamped); window [cB0, cB0+1]
    float S0a[3], S0b[3], S1a[3], S1b[3];
    #pragma unroll
    for (int t = 0; t < 3; t++) {
        const int os = min(ib + t, HH - 1) * WW;
        ldpair<Q>(c.g0 + os, cB0, S0a[t], S0b[t]);
        ldpair<Q>(c.g1 + os, cB0, S1a[t], S1b[t]);
    }

    const float jv0 = (c.j0     < c.jmax) ? 1.0f : 0.0f;
    const float jv1 = (c.j0 + 1 < c.jmax) ? 1.0f : 0.0f;

    float acc = 0.0f;
    #pragma unroll
    for (int r = 0; r < 2; r++) {
        const float rvv = (ib + r < c.imax) ? 1.0f : 0.0f;
        // pixel j0: first term cols (j0, j0+1); second term rows (r+1, r)
        float f0 = c.wx1 * A0x[r] + c.wx2 * A0y[r];
        float f1 = c.wx1 * A1x[r] + c.wx2 * A1y[r];
        float s0 = c.wy1 * S0a[r+1] + c.wy2 * S0a[r];
        float s1 = c.wy1 * S1a[r+1] + c.wy2 * S1a[r];
        float e0 = (f0 - s0) * c.sym_y + (f1 - s1) * c.sym_x;
        acc += (rvv * jv0) * M[r].x * e0 * e0;
        // pixel j0+1: first term cols (j0+1, min(j0+2)); second col cB0+1
        float g0v = c.wx1 * A0y[r] + c.wx2 * A0z[r];
        float g1v = c.wx1 * A1y[r] + c.wx2 * A1z[r];
        float u0 = c.wy1 * S0b[r+1] + c.wy2 * S0b[r];
        float u1 = c.wy1 * S1b[r+1] + c.wy2 * S1b[r];
        float e1 = (g0v - u0) * c.sym_y + (g1v - u1) * c.sym_x;
        acc += (rvv * jv1) * M[r].y * e1 * e1;
    }
    return acc;
}

__global__ __launch_bounds__(256, 4)
void loss_kernel(const float* __restrict__ grid,
                 const float* __restrict__ gt,
                 const float* __restrict__ gd,
                 const float* __restrict__ mask,
                 int B, unsigned int nblocks, float* __restrict__ out)
{
    const int H = HH, W = WW;
    const int b   = blockIdx.y;
    const int tid = threadIdx.x;

    const float dx = -8.0f * gt[2 * b + 0];
    const float dy =  8.0f * gt[2 * b + 1];

    Ctx c;
    c.sym_x = gd[2 * b + 0];
    c.sym_y = gd[2 * b + 1];
    const float dx1f = floorf(dx), dy1f = floorf(dy);
    c.dx1 = (int)dx1f;  c.dy1 = (int)dy1f;  c.dy2 = c.dy1 + 1;
    const int dx2 = c.dx1 + 1;
    c.wx1 = (dx1f + 1.0f) - dx;  c.wx2 = dx - dx1f;
    c.wy1 = (dy1f + 1.0f) - dy;  c.wy2 = dy - dy1f;
    c.w11 = c.wy1 * c.wx1;  c.w12 = c.wy1 * c.wx2;
    c.w21 = c.wy2 * c.wx1;  c.w22 = c.wy2 * c.wx2;
    c.g0 = grid + (size_t)(2 * b + 0) * H * W;
    c.g1 = grid + (size_t)(2 * b + 1) * H * W;
    c.mk = mask + (size_t)b * H * W;
    c.imax = H - c.dy2;
    c.i0 = blockIdx.x * 4;
    c.j0 = 2 * tid;

    float acc;
    float cnt;
    if (dx > 0.0f) {
        c.jmax = W - dx2;
        cnt = (float)c.imax * (float)c.jmax;
        if (c.dx1 & 1) acc = pos_pair<1>(c, c.i0) + pos_pair<1>(c, c.i0 + 2);
        else           acc = pos_pair<0>(c, c.i0) + pos_pair<0>(c, c.i0 + 2);
    } else {
        c.jmax = W + c.dx1;
        cnt = (float)c.imax * (float)c.jmax;
        if ((-c.dx1) & 1) acc = neg_pair<1>(c, c.i0) + neg_pair<1>(c, c.i0 + 2);
        else              acc = neg_pair<0>(c, c.i0) + neg_pair<0>(c, c.i0 + 2);
    }

    // ---- block reduction (8 warps)
    #pragma unroll
    for (int o = 16; o > 0; o >>= 1)
        acc += __shfl_down_sync(0xFFFFFFFFu, acc, o);

    __shared__ float wsum[8];
    const int lane = tid & 31;
    const int warp = tid >> 5;
    if (lane == 0) wsum[warp] = acc;
    __syncthreads();

    if (tid == 0) {
        float s = 0.0f;
        #pragma unroll
        for (int k = 0; k < 8; k++) s += wsum[k];
        double scaled = (double)s / ((double)cnt * (double)B);
        atomicAdd(&g_acc, scaled);

        __threadfence();
        unsigned int prev = atomicInc(&g_ticket, nblocks - 1u);
        if (prev == nblocks - 1u) {
            double total = atomicAdd(&g_acc, 0.0);   // atomic read
            out[0] = (float)total;
            g_acc = 0.0;                              // reset for next replay
            __threadfence();
        }
    }
}

extern "C" void kernel_launch(void* const* d_in, const int* in_sizes, int n_in,
                              void* d_out, int out_size)
{
    const float* grid = (const float*)d_in[0];
    const float* gt   = (const float*)d_in[1];
    const float* gd   = (const float*)d_in[2];
    const float* mask = (const float*)d_in[3];
    float* out = (float*)d_out;

    const int B = in_sizes[1] / 2;   // gt_sym_axis is (B, 2)

    dim3 g(HH / 4, B);
    unsigned int nblocks = (HH / 4) * B;
    loss_kernel<<<g, 256>>>(grid, gt, gd, mask, B, nblocks, out);
}